// round 1
// baseline (speedup 1.0000x reference)
#include <cuda_runtime.h>

#define LAYERS 12
#define NROW   4096
#define DD     16
#define TPB    256
#define ROWS_TOTAL (LAYERS * NROW)
#define NWARP  (TPB / 32)

// Per-layer accumulators: sum of p over rows, sum of log(p+1e-9) over rows,
// and sum of diag terms p·log(p+1e-9). Zero-initialized at module load;
// finalize_kernel re-zeroes them after use so graph replays stay deterministic.
__device__ float g_sp[LAYERS][DD];
__device__ float g_slq[LAYERS][DD];
__device__ float g_diag[LAYERS];

__global__ void __launch_bounds__(TPB) accum_kernel(const float* __restrict__ x) {
    const int row   = blockIdx.x * TPB + threadIdx.x;       // 0..49151
    const int layer = row / NROW;                           // block-uniform (4096 % 256 == 0)

    const float4* xp = reinterpret_cast<const float4*>(x + (size_t)row * DD);
    float4 a0 = xp[0], a1 = xp[1], a2 = xp[2], a3 = xp[3];
    float v[DD] = { a0.x, a0.y, a0.z, a0.w,
                    a1.x, a1.y, a1.z, a1.w,
                    a2.x, a2.y, a2.z, a2.w,
                    a3.x, a3.y, a3.z, a3.w };

    // softmax over D=16
    float m = v[0];
#pragma unroll
    for (int i = 1; i < DD; i++) m = fmaxf(m, v[i]);
    float p[DD];
    float s = 0.f;
#pragma unroll
    for (int i = 0; i < DD; i++) { p[i] = __expf(v[i] - m); s += p[i]; }
    const float inv = 1.0f / s;

    float lq[DD];
    float diag = 0.f;
#pragma unroll
    for (int i = 0; i < DD; i++) {
        p[i]  *= inv;
        lq[i]  = __logf(p[i] + 1e-9f);
        diag   = fmaf(p[i], lq[i], diag);
    }

    // Warp butterfly reduce of the 33 partials
#pragma unroll
    for (int off = 16; off > 0; off >>= 1) {
#pragma unroll
        for (int i = 0; i < DD; i++) {
            p[i]  += __shfl_xor_sync(0xffffffffu, p[i],  off);
            lq[i] += __shfl_xor_sync(0xffffffffu, lq[i], off);
        }
        diag += __shfl_xor_sync(0xffffffffu, diag, off);
    }

    __shared__ float smem[NWARP][34];   // 34 to de-skew banks a bit
    const int wid  = threadIdx.x >> 5;
    const int lane = threadIdx.x & 31;
    if (lane == 0) {
#pragma unroll
        for (int i = 0; i < DD; i++) {
            smem[wid][i]      = p[i];
            smem[wid][DD + i] = lq[i];
        }
        smem[wid][32] = diag;
    }
    __syncthreads();

    if (threadIdx.x < 33) {
        float acc = 0.f;
#pragma unroll
        for (int w = 0; w < NWARP; w++) acc += smem[w][threadIdx.x];
        if (threadIdx.x < DD)
            atomicAdd(&g_sp[layer][threadIdx.x], acc);
        else if (threadIdx.x < 2 * DD)
            atomicAdd(&g_slq[layer][threadIdx.x - DD], acc);
        else
            atomicAdd(&g_diag[layer], acc);
    }
}

__global__ void finalize_kernel(float* __restrict__ out) {
    const int t = threadIdx.x;   // one warp
    float a1 = 0.f, a2 = 0.f;
    if (t < LAYERS) {
        float dot = 0.f, spt = 0.f;
#pragma unroll
        for (int d = 0; d < DD; d++) {
            dot += g_sp[t][d] * g_slq[t][d];
            spt += g_sp[t][d];
        }
        a1 = dot - g_diag[t];                 // (full ce sum - diag) for this layer

        // pm[d] = sp[d] / spt  (mean + renormalize collapse)
        const float invt = 1.0f / spt;
        float ls = 0.f;
#pragma unroll
        for (int d = 0; d < DD; d++)
            ls += __logf(g_sp[t][d] * invt + 1e-8f);
        a2 = -ls / (float)DD;
    }

    // warp reduce across 12 active lanes
#pragma unroll
    for (int off = 16; off > 0; off >>= 1) {
        a1 += __shfl_xor_sync(0xffffffffu, a1, off);
        a2 += __shfl_xor_sync(0xffffffffu, a2, off);
    }

    if (t == 0) {
        const float aux1 = a1 / (2.0f * (float)LAYERS);
        const float aux2 = a2 / (float)LAYERS;
        out[0] = 0.01f * (1.0f * aux1 + aux2);   // ALPHA*(BETA*aux1 + aux2)
    }

    // All lanes have finished reading the accumulators; re-zero for the next
    // graph replay (deterministic replays).
    __syncwarp();
    for (int i = t; i < LAYERS * DD; i += 32) {
        (&g_sp[0][0])[i]  = 0.f;
        (&g_slq[0][0])[i] = 0.f;
    }
    if (t < LAYERS) g_diag[t] = 0.f;
}

extern "C" void kernel_launch(void* const* d_in, const int* in_sizes, int n_in,
                              void* d_out, int out_size) {
    const float* x = (const float*)d_in[0];
    float* out = (float*)d_out;
    accum_kernel<<<ROWS_TOTAL / TPB, TPB>>>(x);
    finalize_kernel<<<1, 32>>>(out);
}

// round 2
// speedup vs baseline: 1.1209x; 1.1209x over previous
#include <cuda_runtime.h>

#define LAYERS 12
#define NROW   4096
#define DD     16
#define TPB    256
#define NBLK   ((LAYERS * NROW) / TPB)   // 192
#define NWARP  (TPB / 32)
#define FULL   0xffffffffu

// Accumulators per layer: [0..15]=sum p, [16..31]=sum log_q, [32]=sum diag.
// Zero at module load; the finalizing block re-zeroes after each run so
// graph replays are deterministic.
__device__ float        g_acc[LAYERS][33];
__device__ unsigned int g_ticket;

__global__ void __launch_bounds__(TPB) fused_kernel(const float* __restrict__ x,
                                                    float* __restrict__ out) {
    const int row   = blockIdx.x * TPB + threadIdx.x;   // 0..49151
    const int layer = row / NROW;                       // block-uniform
    const int lane  = threadIdx.x & 31;
    const int wid   = threadIdx.x >> 5;

    // ---- load row (4 x LDG.128) ----
    const float4* xp = reinterpret_cast<const float4*>(x + (size_t)row * DD);
    float4 a0 = xp[0], a1 = xp[1], a2 = xp[2], a3 = xp[3];
    float v[DD] = { a0.x, a0.y, a0.z, a0.w,  a1.x, a1.y, a1.z, a1.w,
                    a2.x, a2.y, a2.z, a2.w,  a3.x, a3.y, a3.z, a3.w };

    // ---- softmax; log_q via single log: log(p+1e-9) ~= (v-m) - log(s) ----
    float m = v[0];
#pragma unroll
    for (int i = 1; i < DD; i++) m = fmaxf(m, v[i]);
    float e[DD]; float s = 0.f;
#pragma unroll
    for (int i = 0; i < DD; i++) { e[i] = __expf(v[i] - m); s += e[i]; }
    const float inv  = 1.0f / s;
    const float logs = __logf(s);

    // r[0..15] = p[d],  r[16..31] = log_q[d]
    float r[32];
    float diag = 0.f;
#pragma unroll
    for (int i = 0; i < DD; i++) {
        float p  = e[i] * inv;
        float lq = (v[i] - m) - logs;
        r[i]      = p;
        r[i + 16] = lq;
        diag = fmaf(p, lq, diag);
    }

    // ---- recursive-halving warp reduce: lane l ends with warp-sum of r[l] ----
    float t16[16];
    {
        const bool up = (lane & 16) != 0;
#pragma unroll
        for (int i = 0; i < 16; i++) {
            float send = up ? r[i] : r[i + 16];
            float recv = __shfl_xor_sync(FULL, send, 16);
            t16[i] = (up ? r[i + 16] : r[i]) + recv;
        }
    }
    float t8[8];
    {
        const bool up = (lane & 8) != 0;
#pragma unroll
        for (int i = 0; i < 8; i++) {
            float send = up ? t16[i] : t16[i + 8];
            float recv = __shfl_xor_sync(FULL, send, 8);
            t8[i] = (up ? t16[i + 8] : t16[i]) + recv;
        }
    }
    float t4[4];
    {
        const bool up = (lane & 4) != 0;
#pragma unroll
        for (int i = 0; i < 4; i++) {
            float send = up ? t8[i] : t8[i + 4];
            float recv = __shfl_xor_sync(FULL, send, 4);
            t4[i] = (up ? t8[i + 4] : t8[i]) + recv;
        }
    }
    float t2[2];
    {
        const bool up = (lane & 2) != 0;
#pragma unroll
        for (int i = 0; i < 2; i++) {
            float send = up ? t2[i] - t2[i] + t4[i] : t4[i + 2];  // placeholder avoided below
            (void)send;
        }
        // (written out plainly)
        const bool u = up;
        float s0 = u ? t4[0] : t4[2];
        float s1 = u ? t4[1] : t4[3];
        float r0 = __shfl_xor_sync(FULL, s0, 2);
        float r1 = __shfl_xor_sync(FULL, s1, 2);
        t2[0] = (u ? t4[2] : t4[0]) + r0;
        t2[1] = (u ? t4[3] : t4[1]) + r1;
    }
    float tot;
    {
        const bool up = (lane & 1) != 0;
        float send = up ? t2[0] : t2[1];
        float recv = __shfl_xor_sync(FULL, send, 1);
        tot = (up ? t2[1] : t2[0]) + recv;
    }
    // diag: plain butterfly (1 value)
#pragma unroll
    for (int off = 16; off > 0; off >>= 1)
        diag += __shfl_xor_sync(FULL, diag, off);

    // ---- cross-warp reduce in smem, then global atomics ----
    __shared__ float smem[NWARP][34];
    smem[wid][lane] = tot;
    if (lane == 0) smem[wid][32] = diag;
    __syncthreads();

    if (threadIdx.x < 33) {
        float acc = 0.f;
#pragma unroll
        for (int w = 0; w < NWARP; w++) acc += smem[w][threadIdx.x];
        atomicAdd(&g_acc[layer][threadIdx.x], acc);
        __threadfence();
    }
    __syncthreads();

    // ---- ticket: last block finalizes ----
    __shared__ unsigned int s_last;
    if (threadIdx.x == 0)
        s_last = (atomicAdd(&g_ticket, 1u) == (unsigned)(NBLK - 1));
    __syncthreads();
    if (!s_last) return;

    if (threadIdx.x < 32) {
        __threadfence();   // acquire accumulator values written by other SMs
        const int l = lane;
        float a1 = 0.f, a2 = 0.f;
        if (l < LAYERS) {
            float sp[DD], dot = 0.f, spt = 0.f;
#pragma unroll
            for (int d = 0; d < DD; d++) {
                sp[d] = __ldcg(&g_acc[l][d]);
                float lqd = __ldcg(&g_acc[l][DD + d]);
                dot += sp[d] * lqd;
                spt += sp[d];
            }
            a1 = dot - __ldcg(&g_acc[l][32]);
            const float invt = 1.0f / spt;
            float ls = 0.f;
#pragma unroll
            for (int d = 0; d < DD; d++)
                ls += __logf(sp[d] * invt + 1e-8f);
            a2 = -ls / (float)DD;
        }
#pragma unroll
        for (int off = 16; off > 0; off >>= 1) {
            a1 += __shfl_xor_sync(FULL, a1, off);
            a2 += __shfl_xor_sync(FULL, a2, off);
        }
        if (lane == 0) {
            const float aux1 = a1 / (2.0f * (float)LAYERS);
            const float aux2 = a2 / (float)LAYERS;
            out[0] = 0.01f * (aux1 + aux2);   // ALPHA*(BETA*aux1 + aux2)
            g_ticket = 0u;
        }
        // re-zero accumulators for the next graph replay
        for (int i = lane; i < LAYERS * 33; i += 32)
            (&g_acc[0][0])[i] = 0.f;
    }
}

extern "C" void kernel_launch(void* const* d_in, const int* in_sizes, int n_in,
                              void* d_out, int out_size) {
    fused_kernel<<<NBLK, TPB>>>((const float*)d_in[0], (float*)d_out);
}

// round 3
// speedup vs baseline: 1.2250x; 1.0929x over previous
#include <cuda_runtime.h>

#define LAYERS 12
#define NROW   4096
#define DD     16
#define TPB    256
#define NBLK   ((LAYERS * NROW) / TPB)   // 192
#define NWARP  (TPB / 32)
#define FULL   0xffffffffu

// Accumulators per layer: [0..15]=sum p, [16..31]=sum log_q, [32]=sum diag.
// Zero at module load; the finalizing block re-zeroes after each run so
// graph replays are deterministic.
__device__ float        g_acc[LAYERS][33];
__device__ unsigned int g_ticket;

__global__ void __launch_bounds__(TPB) fused_kernel(const float* __restrict__ x,
                                                    float* __restrict__ out) {
    const int row   = blockIdx.x * TPB + threadIdx.x;   // 0..49151
    const int layer = row / NROW;                       // block-uniform
    const int lane  = threadIdx.x & 31;
    const int wid   = threadIdx.x >> 5;

    // ---- load row (4 x LDG.128) ----
    const float4* xp = reinterpret_cast<const float4*>(x + (size_t)row * DD);
    float4 a0 = xp[0], a1 = xp[1], a2 = xp[2], a3 = xp[3];
    float v[DD] = { a0.x, a0.y, a0.z, a0.w,  a1.x, a1.y, a1.z, a1.w,
                    a2.x, a2.y, a2.z, a2.w,  a3.x, a3.y, a3.z, a3.w };

    // ---- softmax; log_q via single log: log(p+1e-9) ~= (v-m) - log(s) ----
    float m = v[0];
#pragma unroll
    for (int i = 1; i < DD; i++) m = fmaxf(m, v[i]);
    float e[DD]; float s = 0.f;
#pragma unroll
    for (int i = 0; i < DD; i++) { e[i] = __expf(v[i] - m); s += e[i]; }
    const float inv  = 1.0f / s;
    const float logs = __logf(s);

    // r[0..15] = p[d],  r[16..31] = log_q[d]
    float r[32];
    float diag = 0.f;
#pragma unroll
    for (int i = 0; i < DD; i++) {
        float p  = e[i] * inv;
        float lq = (v[i] - m) - logs;
        r[i]      = p;
        r[i + 16] = lq;
        diag = fmaf(p, lq, diag);
    }

    // ---- recursive-halving warp reduce: lane l ends with warp-sum of r[l] ----
    float t16[16];
    {
        const bool up = (lane & 16) != 0;
#pragma unroll
        for (int i = 0; i < 16; i++) {
            float send = up ? r[i] : r[i + 16];
            float recv = __shfl_xor_sync(FULL, send, 16);
            t16[i] = (up ? r[i + 16] : r[i]) + recv;
        }
    }
    float t8[8];
    {
        const bool up = (lane & 8) != 0;
#pragma unroll
        for (int i = 0; i < 8; i++) {
            float send = up ? t16[i] : t16[i + 8];
            float recv = __shfl_xor_sync(FULL, send, 8);
            t8[i] = (up ? t16[i + 8] : t16[i]) + recv;
        }
    }
    float t4[4];
    {
        const bool up = (lane & 4) != 0;
#pragma unroll
        for (int i = 0; i < 4; i++) {
            float send = up ? t8[i] : t8[i + 4];
            float recv = __shfl_xor_sync(FULL, send, 4);
            t4[i] = (up ? t8[i + 4] : t8[i]) + recv;
        }
    }
    float t2[2];
    {
        const bool up = (lane & 2) != 0;
#pragma unroll
        for (int i = 0; i < 2; i++) {
            float send = up ? t2[i] - t2[i] + t4[i] : t4[i + 2];  // placeholder avoided below
            (void)send;
        }
        // (written out plainly)
        const bool u = up;
        float s0 = u ? t4[0] : t4[2];
        float s1 = u ? t4[1] : t4[3];
        float r0 = __shfl_xor_sync(FULL, s0, 2);
        float r1 = __shfl_xor_sync(FULL, s1, 2);
        t2[0] = (u ? t4[2] : t4[0]) + r0;
        t2[1] = (u ? t4[3] : t4[1]) + r1;
    }
    float tot;
    {
        const bool up = (lane & 1) != 0;
        float send = up ? t2[0] : t2[1];
        float recv = __shfl_xor_sync(FULL, send, 1);
        tot = (up ? t2[1] : t2[0]) + recv;
    }
    // diag: plain butterfly (1 value)
#pragma unroll
    for (int off = 16; off > 0; off >>= 1)
        diag += __shfl_xor_sync(FULL, diag, off);

    // ---- cross-warp reduce in smem, then global atomics ----
    __shared__ float smem[NWARP][34];
    smem[wid][lane] = tot;
    if (lane == 0) smem[wid][32] = diag;
    __syncthreads();

    if (threadIdx.x < 33) {
        float acc = 0.f;
#pragma unroll
        for (int w = 0; w < NWARP; w++) acc += smem[w][threadIdx.x];
        atomicAdd(&g_acc[layer][threadIdx.x], acc);
        __threadfence();
    }
    __syncthreads();

    // ---- ticket: last block finalizes ----
    __shared__ unsigned int s_last;
    if (threadIdx.x == 0)
        s_last = (atomicAdd(&g_ticket, 1u) == (unsigned)(NBLK - 1));
    __syncthreads();
    if (!s_last) return;

    if (threadIdx.x < 32) {
        __threadfence();   // acquire accumulator values written by other SMs
        const int l = lane;
        float a1 = 0.f, a2 = 0.f;
        if (l < LAYERS) {
            float sp[DD], dot = 0.f, spt = 0.f;
#pragma unroll
            for (int d = 0; d < DD; d++) {
                sp[d] = __ldcg(&g_acc[l][d]);
                float lqd = __ldcg(&g_acc[l][DD + d]);
                dot += sp[d] * lqd;
                spt += sp[d];
            }
            a1 = dot - __ldcg(&g_acc[l][32]);
            const float invt = 1.0f / spt;
            float ls = 0.f;
#pragma unroll
            for (int d = 0; d < DD; d++)
                ls += __logf(sp[d] * invt + 1e-8f);
            a2 = -ls / (float)DD;
        }
#pragma unroll
        for (int off = 16; off > 0; off >>= 1) {
            a1 += __shfl_xor_sync(FULL, a1, off);
            a2 += __shfl_xor_sync(FULL, a2, off);
        }
        if (lane == 0) {
            const float aux1 = a1 / (2.0f * (float)LAYERS);
            const float aux2 = a2 / (float)LAYERS;
            out[0] = 0.01f * (aux1 + aux2);   // ALPHA*(BETA*aux1 + aux2)
            g_ticket = 0u;
        }
        // re-zero accumulators for the next graph replay
        for (int i = lane; i < LAYERS * 33; i += 32)
            (&g_acc[0][0])[i] = 0.f;
    }
}

extern "C" void kernel_launch(void* const* d_in, const int* in_sizes, int n_in,
                              void* d_out, int out_size) {
    fused_kernel<<<NBLK, TPB>>>((const float*)d_in[0], (float*)d_out);
}